// round 1
// baseline (speedup 1.0000x reference)
#include <cuda_runtime.h>
#include <math.h>

#define N_USERS_C 100000
#define N_ITEMS_C 50000
#define N_NODES_C 150000
#define D_C 64
#define NNZ_C 2400000
#define BATCH_C 2048

// Scratch buffers (allocation-free rule: device globals)
__device__ float g_side[N_NODES_C * D_C];
__device__ float g_ego1[N_NODES_C * D_C];
__device__ float g_ego2[N_NODES_C * D_C];

// ---------------------------------------------------------------------------
// zero: clear the scatter accumulator
// ---------------------------------------------------------------------------
__global__ void zero_kernel(float4* __restrict__ p, int n4) {
    int i = blockIdx.x * blockDim.x + threadIdx.x;
    if (i < n4) p[i] = make_float4(0.f, 0.f, 0.f, 0.f);
}

// ---------------------------------------------------------------------------
// SpMM scatter: side[rows[e]] += vals[e] * ego[cols[e]]
// 16 threads per edge, each handles 4 floats via vector red.
// ---------------------------------------------------------------------------
__global__ void spmm_kernel(const int* __restrict__ rows,
                            const int* __restrict__ cols,
                            const float* __restrict__ vals,
                            const float4* __restrict__ ego,
                            float4* __restrict__ side) {
    int gid = blockIdx.x * blockDim.x + threadIdx.x;   // up to 38.4M < 2^31
    int e = gid >> 4;
    if (e >= NNZ_C) return;
    int l = gid & 15;
    int c = cols[e];
    int r = rows[e];
    float v = vals[e];
    float4 m = ego[c * 16 + l];
    m.x *= v; m.y *= v; m.z *= v; m.w *= v;
    float4* dst = side + r * 16 + l;
    asm volatile("red.global.add.v4.f32 [%0], {%1, %2, %3, %4};"
                 :: "l"(dst), "f"(m.x), "f"(m.y), "f"(m.z), "f"(m.w)
                 : "memory");
}

// ---------------------------------------------------------------------------
// Dense layer: out = l2norm(leaky_relu(side@Wg + (ego*side)@Wb + bg + bb))
// Treated as one [M x 128] @ [128 x 64] GEMM with K = [side | ego*side].
// 64-row tiles, 256 threads, 4x4 register blocking, W in smem.
// ---------------------------------------------------------------------------
#define TM_C 64
#define KDIM_C 128
#define INS_C 132   // In tile row stride (floats), padded to dodge bank conflicts

__global__ __launch_bounds__(256)
void dense_kernel(const float4* __restrict__ side,
                  const float4* __restrict__ ego,
                  const float4* __restrict__ Wg, const float* __restrict__ bg,
                  const float4* __restrict__ Wb, const float* __restrict__ bb,
                  float4* __restrict__ out, int numTiles) {
    extern __shared__ float smem[];
    float* Wc   = smem;                       // [128][64] = 8192 floats
    float* In   = smem + KDIM_C * D_C;        // [64][132] = 8448 floats
    float* bsum = In + TM_C * INS_C;          // [64]

    int tid = threadIdx.x;

    // Load combined weight matrix [Wg ; Wb] once per block
#pragma unroll
    for (int i = 0; i < 8; i++) {
        int f = tid + i * 256;               // float4 index 0..2047
        int k = f >> 4, c4 = f & 15;
        float4 w = (k < 64) ? Wg[k * 16 + c4] : Wb[(k - 64) * 16 + c4];
        *(float4*)&Wc[f * 4] = w;            // f*4 == k*64 + c4*4
    }
    if (tid < 64) bsum[tid] = bg[tid] + bb[tid];
    __syncthreads();

    int rg = tid >> 4;   // row group 0..15  (rows rg*4 .. rg*4+3)
    int cg = tid & 15;   // col group 0..15  (cols cg*4 .. cg*4+3)
    float4 bsv = *(float4*)&bsum[cg * 4];

    for (int tile = blockIdx.x; tile < numTiles; tile += gridDim.x) {
        int row0 = tile * TM_C;
        __syncthreads();   // previous tile's compute done before overwriting In

        // Stage input tile: In[r][0:64] = side row, In[r][64:128] = ego*side
#pragma unroll
        for (int i = 0; i < 4; i++) {
            int f = tid + i * 256;           // float4 index over 64x16
            int r = f >> 4, k4 = f & 15;
            float4 s  = make_float4(0.f, 0.f, 0.f, 0.f);
            float4 pr = make_float4(0.f, 0.f, 0.f, 0.f);
            int grow = row0 + r;
            if (grow < N_NODES_C) {
                s = side[grow * 16 + k4];
                float4 e = ego[grow * 16 + k4];
                pr = make_float4(s.x * e.x, s.y * e.y, s.z * e.z, s.w * e.w);
            }
            *(float4*)&In[r * INS_C + k4 * 4]      = s;
            *(float4*)&In[r * INS_C + 64 + k4 * 4] = pr;
        }
        __syncthreads();

        float acc[4][4];
#pragma unroll
        for (int i = 0; i < 4; i++)
#pragma unroll
            for (int j = 0; j < 4; j++) acc[i][j] = 0.f;

        const float* Inr = &In[(rg * 4) * INS_C];
#pragma unroll 4
        for (int k = 0; k < KDIM_C; k++) {
            float a0 = Inr[k];
            float a1 = Inr[INS_C + k];
            float a2 = Inr[2 * INS_C + k];
            float a3 = Inr[3 * INS_C + k];
            float4 b = *(const float4*)&Wc[k * 64 + cg * 4];
            acc[0][0] += a0 * b.x; acc[0][1] += a0 * b.y; acc[0][2] += a0 * b.z; acc[0][3] += a0 * b.w;
            acc[1][0] += a1 * b.x; acc[1][1] += a1 * b.y; acc[1][2] += a1 * b.z; acc[1][3] += a1 * b.w;
            acc[2][0] += a2 * b.x; acc[2][1] += a2 * b.y; acc[2][2] += a2 * b.z; acc[2][3] += a2 * b.w;
            acc[3][0] += a3 * b.x; acc[3][1] += a3 * b.y; acc[3][2] += a3 * b.z; acc[3][3] += a3 * b.w;
        }

        // Epilogue: bias, leaky_relu(0.2), per-row L2 normalize, store
#pragma unroll
        for (int i = 0; i < 4; i++) {
            float v0 = acc[i][0] + bsv.x;
            float v1 = acc[i][1] + bsv.y;
            float v2 = acc[i][2] + bsv.z;
            float v3 = acc[i][3] + bsv.w;
            v0 = (v0 > 0.f) ? v0 : 0.2f * v0;
            v1 = (v1 > 0.f) ? v1 : 0.2f * v1;
            v2 = (v2 > 0.f) ? v2 : 0.2f * v2;
            v3 = (v3 > 0.f) ? v3 : 0.2f * v3;
            float ss = v0 * v0 + v1 * v1 + v2 * v2 + v3 * v3;
            // reduce across the 16 lanes owning this row (same half-warp)
#pragma unroll
            for (int o = 8; o > 0; o >>= 1)
                ss += __shfl_xor_sync(0xffffffffu, ss, o);
            float nrm = sqrtf(ss);
            float scl = 1.0f / fmaxf(nrm, 1e-12f);
            int grow = row0 + rg * 4 + i;
            if (grow < N_NODES_C)
                out[grow * 16 + cg] = make_float4(v0 * scl, v1 * scl, v2 * scl, v3 * scl);
        }
    }
}

// ---------------------------------------------------------------------------
// gamma[b] = sum over 3 embeddings of dot(emb[u], emb[N_USERS+item])
// one warp per batch element
// ---------------------------------------------------------------------------
__global__ void gamma_kernel(const float* __restrict__ x,
                             const int* __restrict__ users,
                             const int* __restrict__ items,
                             float* __restrict__ out) {
    int b = blockIdx.x * 8 + (threadIdx.x >> 5);
    if (b >= BATCH_C) return;
    int lane = threadIdx.x & 31;
    int u  = users[b];
    int it = N_USERS_C + items[b];
    long long ub = (long long)u * D_C, ib = (long long)it * D_C;
    float acc = 0.f;
    acc += x[ub + lane]      * x[ib + lane];
    acc += x[ub + 32 + lane] * x[ib + 32 + lane];
    acc += g_ego1[ub + lane]      * g_ego1[ib + lane];
    acc += g_ego1[ub + 32 + lane] * g_ego1[ib + 32 + lane];
    acc += g_ego2[ub + lane]      * g_ego2[ib + lane];
    acc += g_ego2[ub + 32 + lane] * g_ego2[ib + 32 + lane];
#pragma unroll
    for (int o = 16; o > 0; o >>= 1)
        acc += __shfl_xor_sync(0xffffffffu, acc, o);
    if (lane == 0) out[b] = acc;
}

// ---------------------------------------------------------------------------
extern "C" void kernel_launch(void* const* d_in, const int* in_sizes, int n_in,
                              void* d_out, int out_size) {
    const int*   rows = (const int*)d_in[0];
    const int*   cols = (const int*)d_in[1];
    const float* vals = (const float*)d_in[2];
    const float* x    = (const float*)d_in[3];

    const float *Wg0, *bg0, *Wb0, *bb0, *Wg1, *bg1, *Wb1, *bb1;
    const int *users, *items;
    if (in_sizes[4] == BATCH_C) {
        // dict order: users, items, then weights
        users = (const int*)d_in[4];
        items = (const int*)d_in[5];
        Wg0 = (const float*)d_in[6];  bg0 = (const float*)d_in[7];
        Wb0 = (const float*)d_in[8];  bb0 = (const float*)d_in[9];
        Wg1 = (const float*)d_in[10]; bg1 = (const float*)d_in[11];
        Wb1 = (const float*)d_in[12]; bb1 = (const float*)d_in[13];
    } else {
        // signature order: weights, then users, items
        Wg0 = (const float*)d_in[4];  bg0 = (const float*)d_in[5];
        Wb0 = (const float*)d_in[6];  bb0 = (const float*)d_in[7];
        Wg1 = (const float*)d_in[8];  bg1 = (const float*)d_in[9];
        Wb1 = (const float*)d_in[10]; bb1 = (const float*)d_in[11];
        users = (const int*)d_in[12];
        items = (const int*)d_in[13];
    }

    float *side, *ego1, *ego2;
    cudaGetSymbolAddress((void**)&side, g_side);
    cudaGetSymbolAddress((void**)&ego1, g_ego1);
    cudaGetSymbolAddress((void**)&ego2, g_ego2);

    int smemBytes = (KDIM_C * D_C + TM_C * INS_C + 64) * (int)sizeof(float); // 66816
    cudaFuncSetAttribute(dense_kernel, cudaFuncAttributeMaxDynamicSharedMemorySize, smemBytes);

    int numTiles = (N_NODES_C + TM_C - 1) / TM_C;   // 2344
    int z4 = N_NODES_C * 16;                        // float4 count
    int zeroBlocks = (z4 + 255) / 256;
    int spmmBlocks = (NNZ_C * 16) / 256;            // 150000 exactly

    // Layer 1
    zero_kernel<<<zeroBlocks, 256>>>((float4*)side, z4);
    spmm_kernel<<<spmmBlocks, 256>>>(rows, cols, vals, (const float4*)x, (float4*)side);
    dense_kernel<<<592, 256, smemBytes>>>((const float4*)side, (const float4*)x,
                                          (const float4*)Wg0, bg0,
                                          (const float4*)Wb0, bb0,
                                          (float4*)ego1, numTiles);
    // Layer 2
    zero_kernel<<<zeroBlocks, 256>>>((float4*)side, z4);
    spmm_kernel<<<spmmBlocks, 256>>>(rows, cols, vals, (const float4*)ego1, (float4*)side);
    dense_kernel<<<592, 256, smemBytes>>>((const float4*)side, (const float4*)ego1,
                                          (const float4*)Wg1, bg1,
                                          (const float4*)Wb1, bb1,
                                          (float4*)ego2, numTiles);
    // Final BPR scores
    gamma_kernel<<<BATCH_C / 8, 256>>>(x, users, items, (float*)d_out);
}